// round 10
// baseline (speedup 1.0000x reference)
#include <cuda_runtime.h>

// InterConv: B=2048, F=39, E=64, C=64, P=741
// out[b, c*P + p] = relu( U[c][ii[p]] + V[c][jj[p]] ),  U = x@Wi^T + bias, V = x@Wj^T
//
// smem (floats), 45.3 KB -> 4 CTAs/SM:
//   phase 0/1: xs [0,2624)   Wi [2624,6976) + Wj [6976,11328)   (stride 68)
//   phase 2:   Uc [0,2624)   VI [2624,5504)  tab32 [5504,6248)  tabp [6248,7912)
//
// Phase 2: 4-wide blocks. Rows r and r+32 share p0=(27r)&31; per pair, 6 u64
// packed block-entries are preloaded into registers. Each block: 2 u-LDS,
// 4 v-LDS (VI interleaved -> consecutive), 1 STG.128; u-select via baked bits.

#define FN 39
#define EN 64
#define CN 64
#define PN 741            // 39*38/2
#define OUTB (CN * PN)    // 47424 floats per batch
#define THREADS 256

#define A_OFF   0
#define B_OFF   2624
#define VI_OFF  B_OFF                 // [c][45], slot (j&3)*11 + (j>>2)
#define T32_OFF (B_OFF + CN*45)       // 5504: u32 tab, 741 entries (744 floats)
#define TP_OFF  (T32_OFF + 744)       // 6248: u64 packed blocks, 4 copies x 208
#define SMEM_FLOATS 11328
#define SMEM_BYTES  (SMEM_FLOATS * 4)

// packed fp32x2 FMA (Blackwell; exact fp32 semantics, 2x FFMA throughput)
#define FMA_F32X2(acc, a, b) \
    asm("fma.rn.f32x2 %0, %1, %2, %0;" : "+l"(acc) : "l"(a), "l"(b))

extern __shared__ float smem[];

__global__ void __launch_bounds__(THREADS, 4)
interconv_kernel(const float* __restrict__ x,
                 const float* __restrict__ W,
                 const float* __restrict__ bias,
                 float* __restrict__ out)
{
    const int tid = threadIdx.x;
    const long long b = blockIdx.x;

    // ---- Phase 0: stage x and W (float4) ---------------------------------
    {
        float4* xs4 = (float4*)(smem + A_OFF);
        const float4* xb4 = (const float4*)(x + b * (long long)(FN * EN));
        #pragma unroll
        for (int it = 0; it < 3; it++) {
            int idx = tid + it * THREADS;
            if (idx < (FN * EN) / 4) xs4[idx] = xb4[idx];
        }
        if (tid < EN)                              // zero pad row f=39
            smem[A_OFF + FN * EN + tid] = 0.f;

        float4* Wi4 = (float4*)(smem + B_OFF);     // [c][17]
        float4* Wj4 = Wi4 + CN * 17;
        const float4* Wg4 = (const float4*)W;
        #pragma unroll
        for (int it = 0; it < 8; it++) {
            int idx = tid + it * THREADS;          // 2048 float4 total
            int c = idx >> 5, q = idx & 31;
            float4 w = Wg4[idx];
            if (q < 16) Wi4[c * 17 + q] = w;
            else        Wj4[c * 17 + (q - 16)] = w;
        }
    }
    __syncthreads();

    // ---- Phase 1: U = x @ Wi^T + b, V = x @ Wj^T  (f32x2, regs only) -----
    const int c  = tid & 63;
    const int fg = tid >> 6;

    unsigned long long au[10], av[10];
    #pragma unroll
    for (int k = 0; k < 10; k++) { au[k] = 0ull; av[k] = 0ull; }

    {
        const ulonglong2* xs2 = (const ulonglong2*)(smem + A_OFF);   // [f][16]
        const ulonglong2* Wi2 = (const ulonglong2*)(smem + B_OFF);   // [c][17]
        const ulonglong2* Wj2 = Wi2 + CN * 17;

        #pragma unroll
        for (int e4 = 0; e4 < 16; e4++) {
            ulonglong2 wi = Wi2[c * 17 + e4];
            ulonglong2 wj = Wj2[c * 17 + e4];
            #pragma unroll
            for (int k = 0; k < 10; k++) {
                ulonglong2 xv = xs2[(fg + 4 * k) * 16 + e4];  // f=39 row is zeros
                FMA_F32X2(au[k], xv.x, wi.x);
                FMA_F32X2(au[k], xv.y, wi.y);
                FMA_F32X2(av[k], xv.x, wj.x);
                FMA_F32X2(av[k], xv.y, wj.y);
            }
        }
    }
    __syncthreads();   // all xs/W reads done; safe to overlay

    // ---- Phase 1b: write Uc / VI + build u32 tab -------------------------
    float* Uc = smem + A_OFF;                 // [c][41]
    float* VI = smem + VI_OFF;                // [c][45], slot (f&3)*11+(f>>2)
    unsigned* tab32 = (unsigned*)(smem + T32_OFF);
    unsigned long long* tabp = (unsigned long long*)(smem + TP_OFF);

    {
        const float bc = __ldg(bias + c);
        #pragma unroll
        for (int k = 0; k < 10; k++) {
            int f = fg + 4 * k;               // f<=39 (pads are never read)
            float ulo = __uint_as_float((unsigned)au[k]);
            float uhi = __uint_as_float((unsigned)(au[k] >> 32));
            float vlo = __uint_as_float((unsigned)av[k]);
            float vhi = __uint_as_float((unsigned)(av[k] >> 32));
            Uc[c * 41 + f] = ulo + uhi + bc;  // bias folded into U
            VI[c * 45 + (f & 3) * 11 + (f >> 2)] = vlo + vhi;
        }
        // u32 tab: low16 = i*4, high16 = vi(j)*4 (byte offsets; both <= 168)
        for (int p = tid; p < PN; p += THREADS) {
            int i = 0, rem = p;
            while (rem >= FN - 1 - i) { rem -= FN - 1 - i; i++; }
            int j = i + 1 + rem;
            unsigned vio = (unsigned)((((j & 3) * 11) + (j >> 2)) * 4);
            tab32[p] = (unsigned)(i * 4) | (vio << 16);
        }
    }
    __syncthreads();

    // ---- Phase 1c: compose packed block table from tab32 -----------------
    // tabp[s*208+m] covers p = 4m+s .. 4m+s+3:
    //   low32  = v0 | v1<<8 | v2<<16 | v3<<24           (VI byte offsets)
    //   high32 = uA | uB<<8 | (i1!=i0)<<16 | (i2!=i0)<<17  (Uc byte offsets)
    for (int idx = tid; idx < 832; idx += THREADS) {
        int s = idx / 208, m = idx - s * 208;
        int p = 4 * m + s;
        unsigned long long e = 0;
        if (p + 3 <= 740) {
            unsigned e0 = tab32[p], e1 = tab32[p + 1];
            unsigned e2 = tab32[p + 2], e3 = tab32[p + 3];
            unsigned vpack = (e0 >> 16) | ((e1 >> 16) << 8)
                           | ((e2 >> 16) << 16) | ((e3 >> 16) << 24);
            unsigned i0 = e0 & 255u, i1 = e1 & 255u;
            unsigned i2 = e2 & 255u, i3 = e3 & 255u;
            unsigned upack = i0 | (i3 << 8)
                           | ((i1 != i0 ? 1u : 0u) << 16)
                           | ((i2 != i0 ? 1u : 0u) << 17);
            e = (unsigned long long)upack << 32 | vpack;
        }
        tabp[idx] = e;
    }
    __syncthreads();

    // ---- Phase 2: 4-wide expansion + relu ---------------------------------
    const int lane = tid & 31;
    const int wrp  = tid >> 5;
    float* outb = out + b * (long long)OUTB;

    #pragma unroll 1
    for (int k = 0; k < 4; k++) {
        const int r  = wrp * 4 + k;           // rows r and r+32 share p0
        const int p0 = (27 * r) & 31;
        const int s  = p0 & 3, q = p0 >> 2;

        // preload 6 packed block entries (blocks bb = it*32 + lane)
        unsigned long long tw[6];
        {
            const unsigned long long* tp = tabp + s * 208 + q + lane;
            #pragma unroll
            for (int it = 0; it < 6; it++) tw[it] = tp[it * 32];
        }

        #pragma unroll
        for (int h = 0; h < 2; h++) {
            const int gc = r + 32 * h;
            const char* bu = (const char*)(Uc + gc * 41);
            const char* bv = (const char*)(VI + gc * 45);
            float* po = outb + gc * PN;

            // head: p in [0, p0)
            if (lane < p0) {
                unsigned t = tab32[lane];
                float u = *(const float*)(bu + (t & 0xFFFFu));
                float v = *(const float*)(bv + (t >> 16));
                __stcs(po + lane, fmaxf(u + v, 0.f));
            }

            // main: 176 blocks of 4 (it=0..4 full, it=5 for lane<16)
            float* pom = po + p0;
            #pragma unroll
            for (int it = 0; it < 6; it++) {
                if (it < 5 || lane < 16) {
                    unsigned tv = (unsigned)tw[it];
                    unsigned tu = (unsigned)(tw[it] >> 32);
                    float uA = *(const float*)(bu + (tu & 255u));
                    float uB = *(const float*)(bu + ((tu >> 8) & 255u));
                    float v0 = *(const float*)(bv + (tv & 255u));
                    float v1 = *(const float*)(bv + ((tv >> 8) & 255u));
                    float v2 = *(const float*)(bv + ((tv >> 16) & 255u));
                    float v3 = *(const float*)(bv + (tv >> 24));
                    float u1 = (tu & 0x10000u) ? uB : uA;
                    float u2 = (tu & 0x20000u) ? uB : uA;
                    float4 o;
                    o.x = fmaxf(uA + v0, 0.f);
                    o.y = fmaxf(u1 + v1, 0.f);
                    o.z = fmaxf(u2 + v2, 0.f);
                    o.w = fmaxf(uB + v3, 0.f);
                    __stcs((float4*)(pom + 4 * (it * 32 + lane)), o);
                }
            }

            // tail: p in [p0+704, 741)
            int p = p0 + 704 + lane;
            if (p < PN) {
                unsigned t = tab32[p];
                float u = *(const float*)(bu + (t & 0xFFFFu));
                float v = *(const float*)(bv + (t >> 16));
                __stcs(po + p, fmaxf(u + v, 0.f));
            }
            p += 32;
            if (p < PN) {
                unsigned t = tab32[p];
                float u = *(const float*)(bu + (t & 0xFFFFu));
                float v = *(const float*)(bv + (t >> 16));
                __stcs(po + p, fmaxf(u + v, 0.f));
            }
        }
    }
}

extern "C" void kernel_launch(void* const* d_in, const int* in_sizes, int n_in,
                              void* d_out, int out_size)
{
    const float* x    = (const float*)d_in[0];
    const float* W    = (const float*)d_in[1];
    const float* bias = (const float*)d_in[2];
    float* out = (float*)d_out;

    const int B = in_sizes[0] / (FN * EN);   // 2048

    cudaFuncSetAttribute(interconv_kernel,
                         cudaFuncAttributeMaxDynamicSharedMemorySize, SMEM_BYTES);
    interconv_kernel<<<B, THREADS, SMEM_BYTES>>>(x, W, bias, out);
}